// round 4
// baseline (speedup 1.0000x reference)
#include <cuda_runtime.h>
#include <math.h>

// IN_FEATURES=128, UNITS=512, BATCH=2048, out = [x (2048*128) ; logdet (2048)]
#define R        16
#define RP       20      // padded per-unit row stride (floats)
#define THREADS  512
#define NBLK     128

typedef unsigned long long ull;

__device__ float g_W1c[128 * 512];   // [i][p]
__device__ float g_W2t[512 * 512];   // [p][q]
__device__ float g_W3t[512 * 256];   // [q][o]
__device__ float g_A1init[512];
__device__ float g_A2init[512];
__device__ float g_Zinit[256];

__device__ __forceinline__ int posOf(int k) {
    int d = k % 127;
    int j = k / 127;
    return d * 4 + (d < 4 ? d : 4) + j;
}
__device__ __forceinline__ int origOf(int q) {
    int d, j;
    if (q < 20) { d = q / 5; j = q - d * 5; }
    else        { d = 4 + ((q - 20) >> 2); j = (q - 20) & 3; }
    return d + 127 * j;
}

// ---------------- prologue ----------------
__global__ void k_transform(const float* __restrict__ W1, const float* __restrict__ b1,
                            const float* __restrict__ W2, const float* __restrict__ W3,
                            const float* __restrict__ m1, const float* __restrict__ m2,
                            const float* __restrict__ m3) {
    int idx = blockIdx.x * blockDim.x + threadIdx.x;
    int stride = gridDim.x * blockDim.x;
    for (int t = idx; t < 512 * 128; t += stride) {
        int k = t >> 7, i = t & 127;
        g_W1c[i * 512 + posOf(k)] = W1[t] * m1[t];
    }
    for (int t = idx; t < 512 * 512; t += stride) {
        int m = t >> 9, k = t & 511;
        g_W2t[posOf(k) * 512 + posOf(m)] = W2[t] * m2[t];
    }
    for (int t = idx; t < 256 * 512; t += stride) {
        int o = t >> 9, m = t & 511;
        g_W3t[posOf(m) * 256 + o] = W3[t] * m3[t];
    }
    for (int t = idx; t < 512; t += stride)
        g_A1init[posOf(t)] = b1[t];
}

__global__ void k_init(const float* __restrict__ b2, const float* __restrict__ b3) {
    __shared__ float h1[512], h2[512];
    int t = threadIdx.x;
    h1[t] = fmaxf(g_A1init[t], 0.f);
    __syncthreads();
    {
        float acc = b2[origOf(t)];
        for (int p = 0; p < 512; ++p) acc = fmaf(g_W2t[p * 512 + t], h1[p], acc);
        g_A2init[t] = acc;
        h2[t] = fmaxf(acc, 0.f);
    }
    __syncthreads();
    if (t < 256) {
        float a = b3[t];
        for (int q = 0; q < 512; ++q) a = fmaf(g_W3t[q * 256 + t], h2[q], a);
        g_Zinit[t] = a;
    }
}

// ---- packed f32x2 helpers ----
__device__ __forceinline__ ull dup2(float w) {
    ull r; asm("mov.b64 %0, {%1, %1};" : "=l"(r) : "f"(w)); return r;
}
__device__ __forceinline__ float2 u2f(ull v) {
    float2 f; asm("mov.b64 {%0, %1}, %2;" : "=f"(f.x), "=f"(f.y) : "l"(v)); return f;
}
#define PFMA(acc, w, v) asm("fma.rn.f32x2 %0, %1, %2, %0;" : "+l"(acc) : "l"(w), "l"(v))
__device__ __forceinline__ void addp(ull& a, ull b) {
    asm("add.rn.f32x2 %0, %0, %1;" : "+l"(a) : "l"(b));
}
// dual-column FMA: one 16-row vector feeds two accumulator sets
__device__ __forceinline__ void fma_dual(ull* a0, ull* a1, const float* base, float w0, float w1) {
    ull W0 = dup2(w0), W1 = dup2(w1);
    const ulonglong2* v = (const ulonglong2*)base;
    ulonglong2 x = v[0], y = v[1], z = v[2], w = v[3];
    PFMA(a0[0], W0, x.x); PFMA(a1[0], W1, x.x);
    PFMA(a0[1], W0, x.y); PFMA(a1[1], W1, x.y);
    PFMA(a0[2], W0, y.x); PFMA(a1[2], W1, y.x);
    PFMA(a0[3], W0, y.y); PFMA(a1[3], W1, y.y);
    PFMA(a0[4], W0, z.x); PFMA(a1[4], W1, z.x);
    PFMA(a0[5], W0, z.y); PFMA(a1[5], W1, z.y);
    PFMA(a0[6], W0, w.x); PFMA(a1[6], W1, w.x);
    PFMA(a0[7], W0, w.y); PFMA(a1[7], W1, w.y);
}

// ---------------- main persistent kernel ----------------
__global__ void __launch_bounds__(THREADS, 1)
k_main(const float* __restrict__ u, float* __restrict__ out) {
    extern __shared__ float sm[];
    float* A1  = sm;                 // 512*RP
    float* A2  = A1 + 512 * RP;
    float* DH1 = A2 + 512 * RP;
    float* DH2 = DH1 + 512 * RP;
    float* Z   = DH2 + 512 * RP;     // 256*RP
    float* us  = Z + 256 * RP;       // 128*16  u transposed [i][r]
    float* xs  = us + 128 * 16;      // 128*16  x transposed [i][r]

    const int tid  = threadIdx.x;
    const int lane = tid & 31;
    const int row0 = blockIdx.x * R;

    for (int t = tid; t < R * 128; t += THREADS) {
        int r = t >> 7, c = t & 127;
        us[c * 16 + r] = u[(row0 + r) * 128 + c];
    }
    for (int t = tid; t < 512; t += THREADS) {
        float a1 = g_A1init[t], a2 = g_A2init[t];
#pragma unroll
        for (int r = 0; r < R; ++r) { A1[t * RP + r] = a1; A2[t * RP + r] = a2; }
    }
    for (int t = tid; t < 256; t += THREADS) {
        float z = g_Zinit[t];
#pragma unroll
        for (int r = 0; r < R; ++r) Z[t * RP + r] = z;
    }
    float ldacc = 0.f;
    __syncthreads();

    for (int i = 0; i < 128; ++i) {
        // ---- (a) every warp computes x_i redundantly (no barrier needed) ----
        float xval = 0.f;
        if (lane < 16) {
            float mu = Z[i * RP + lane];
            float sg = Z[(128 + i) * RP + lane];
            xval = us[i * 16 + lane] * __expf(sg) + mu;
            xs[i * 16 + lane] = xval;          // benign duplicate write (identical value)
            if (tid < 16) ldacc += sg;
        }
        if (i == 127) break;

        const int s    = 4 * i + (i < 4 ? i : 4);
        const int cols = 512 - s;

        // ---- (c) layer-1 suffix update ----
        {
            int r = tid & 15;
            float x = __shfl_sync(0xffffffffu, xval, r);
            for (int p = s + (tid >> 4); p < 512; p += THREADS / 16) {
                float w   = g_W1c[i * 512 + p];
                float old = A1[p * RP + r];
                float nw  = fmaf(w, x, old);
                A1[p * RP + r]  = nw;
                DH1[p * RP + r] = fmaxf(nw, 0.f) - fmaxf(old, 0.f);
            }
        }
        __syncthreads();

        // ---- (d) A2[q,:] += sum_p W2t[p][q] * DH1[p,:]  (q-pairs, S-way p-split) ----
        {
            int npairs = (cols + 1) >> 1;
            int S = 2;
            while (S < 32 && npairs * (S << 1) <= THREADS) S <<= 1;
            int lg  = __popc(S - 1);
            int act = (npairs * S + 31) & ~31;
            if (tid < act) {
                int split = tid & (S - 1);
                int jj    = tid >> lg;
                int j     = jj < npairs ? jj : npairs - 1;
                int q0    = s + 2 * j;
                bool two  = (q0 + 1) < 512;
                int p0    = s + (split * cols) / S;
                int p1    = s + ((split + 1) * cols) / S;
                ull a0[8], a1[8];
#pragma unroll
                for (int k = 0; k < 8; ++k) { a0[k] = 0ull; a1[k] = 0ull; }
#pragma unroll 2
                for (int p = p0; p < p1; ++p) {
                    float w0 = g_W2t[p * 512 + q0];
                    float w1 = two ? g_W2t[p * 512 + q0 + 1] : 0.f;
                    fma_dual(a0, a1, DH1 + p * RP, w0, w1);
                }
                for (int off = 1; off < S; off <<= 1) {
#pragma unroll
                    for (int k = 0; k < 8; ++k) {
                        addp(a0[k], __shfl_xor_sync(0xffffffffu, a0[k], off));
                        addp(a1[k], __shfl_xor_sync(0xffffffffu, a1[k], off));
                    }
                }
                if (split == 0 && jj < npairs) {
#pragma unroll
                    for (int k = 0; k < 8; ++k) {
                        float2 a = u2f(a0[k]);
                        float o0 = A2[q0 * RP + 2 * k],     n0 = o0 + a.x;
                        float o1 = A2[q0 * RP + 2 * k + 1], n1 = o1 + a.y;
                        A2[q0 * RP + 2 * k]      = n0;
                        A2[q0 * RP + 2 * k + 1]  = n1;
                        DH2[q0 * RP + 2 * k]     = fmaxf(n0, 0.f) - fmaxf(o0, 0.f);
                        DH2[q0 * RP + 2 * k + 1] = fmaxf(n1, 0.f) - fmaxf(o1, 0.f);
                    }
                    if (two) {
                        int q1 = q0 + 1;
#pragma unroll
                        for (int k = 0; k < 8; ++k) {
                            float2 a = u2f(a1[k]);
                            float o0 = A2[q1 * RP + 2 * k],     n0 = o0 + a.x;
                            float o1 = A2[q1 * RP + 2 * k + 1], n1 = o1 + a.y;
                            A2[q1 * RP + 2 * k]      = n0;
                            A2[q1 * RP + 2 * k + 1]  = n1;
                            DH2[q1 * RP + 2 * k]     = fmaxf(n0, 0.f) - fmaxf(o0, 0.f);
                            DH2[q1 * RP + 2 * k + 1] = fmaxf(n1, 0.f) - fmaxf(o1, 0.f);
                        }
                    }
                }
            }
        }
        __syncthreads();

        // ---- (e) z update: thread handles (mu_o, sigma_o), S-way q-split ----
        {
            int hc = 127 - i;
            int S = 2;
            while (S < 32 && hc * (S << 1) <= THREADS) S <<= 1;
            int lg  = __popc(S - 1);
            int act = (hc * S + 31) & ~31;
            if (tid < act) {
                int split = tid & (S - 1);
                int jj    = tid >> lg;
                int j     = jj < hc ? jj : hc - 1;
                int o     = i + 1 + j;              // mu column; sigma = o+128
                int q0r   = s + (split * cols) / S;
                int q1r   = s + ((split + 1) * cols) / S;
                ull am[8], asg[8];
#pragma unroll
                for (int k = 0; k < 8; ++k) { am[k] = 0ull; asg[k] = 0ull; }
#pragma unroll 2
                for (int q = q0r; q < q1r; ++q) {
                    float wm = g_W3t[q * 256 + o];
                    float ws = g_W3t[q * 256 + o + 128];
                    fma_dual(am, asg, DH2 + q * RP, wm, ws);
                }
                for (int off = 1; off < S; off <<= 1) {
#pragma unroll
                    for (int k = 0; k < 8; ++k) {
                        addp(am[k],  __shfl_xor_sync(0xffffffffu, am[k],  off));
                        addp(asg[k], __shfl_xor_sync(0xffffffffu, asg[k], off));
                    }
                }
                if (split == 0 && jj < hc) {
#pragma unroll
                    for (int k = 0; k < 8; ++k) {
                        float2 a = u2f(am[k]);
                        Z[o * RP + 2 * k]     += a.x;
                        Z[o * RP + 2 * k + 1] += a.y;
                        float2 b = u2f(asg[k]);
                        Z[(o + 128) * RP + 2 * k]     += b.x;
                        Z[(o + 128) * RP + 2 * k + 1] += b.y;
                    }
                }
            }
        }
        __syncthreads();
    }

    __syncthreads();
    // coalesced writeout of x
    for (int t = tid; t < R * 128; t += THREADS) {
        int r = t >> 7, c = t & 127;
        out[(row0 + r) * 128 + c] = xs[c * 16 + r];
    }
    if (tid < 16) out[2048 * 128 + row0 + tid] = ldacc;
}

extern "C" void kernel_launch(void* const* d_in, const int* in_sizes, int n_in,
                              void* d_out, int out_size) {
    const float* u  = (const float*)d_in[0];
    const float* W1 = (const float*)d_in[1];
    const float* b1 = (const float*)d_in[2];
    const float* W2 = (const float*)d_in[3];
    const float* b2 = (const float*)d_in[4];
    const float* W3 = (const float*)d_in[5];
    const float* b3 = (const float*)d_in[6];
    const float* m1 = (const float*)d_in[7];
    const float* m2 = (const float*)d_in[8];
    const float* m3 = (const float*)d_in[9];
    float* out = (float*)d_out;

    const size_t smem = (size_t)(512 * RP * 4 + 256 * RP + 128 * 16 * 2) * sizeof(float);
    cudaFuncSetAttribute(k_main, cudaFuncAttributeMaxDynamicSharedMemorySize, (int)smem);

    k_transform<<<256, 256>>>(W1, b1, W2, W3, m1, m2, m3);
    k_init<<<1, 512>>>(b2, b3);
    k_main<<<NBLK, THREADS, smem>>>(u, out);
}

// round 5
// speedup vs baseline: 1.0955x; 1.0955x over previous
#include <cuda_runtime.h>
#include <math.h>

// IN_FEATURES=128, UNITS=512, BATCH=2048, out = [x (2048*128) ; logdet (2048)]
#define R        16
#define RP       20      // padded per-unit row stride (floats)
#define THREADS  512
#define NBLK     128

typedef unsigned long long ull;

__device__ float g_W1c[128 * 512];   // [i][p]
__device__ float g_W2t[512 * 512];   // [p][q]
__device__ float g_W3t[512 * 256];   // [q][o]
__device__ float g_A1init[512];      // b1 permuted

__device__ __forceinline__ int posOf(int k) {
    int d = k % 127;
    int j = k / 127;
    return d * 4 + (d < 4 ? d : 4) + j;
}
__device__ __forceinline__ int origOf(int q) {
    int d, j;
    if (q < 20) { d = q / 5; j = q - d * 5; }
    else        { d = 4 + ((q - 20) >> 2); j = (q - 20) & 3; }
    return d + 127 * j;
}

// ---------------- prologue: mask + permute + transpose ----------------
__global__ void k_transform(const float* __restrict__ W1, const float* __restrict__ b1,
                            const float* __restrict__ W2, const float* __restrict__ W3,
                            const float* __restrict__ m1, const float* __restrict__ m2,
                            const float* __restrict__ m3) {
    int idx = blockIdx.x * blockDim.x + threadIdx.x;
    int stride = gridDim.x * blockDim.x;
    for (int t = idx; t < 512 * 128; t += stride) {
        int k = t >> 7, i = t & 127;
        g_W1c[i * 512 + posOf(k)] = W1[t] * m1[t];
    }
    for (int t = idx; t < 512 * 512; t += stride) {
        int m = t >> 9, k = t & 511;
        g_W2t[posOf(k) * 512 + posOf(m)] = W2[t] * m2[t];
    }
    for (int t = idx; t < 256 * 512; t += stride) {
        int o = t >> 9, m = t & 511;
        g_W3t[posOf(m) * 256 + o] = W3[t] * m3[t];
    }
    for (int t = idx; t < 512; t += stride)
        g_A1init[posOf(t)] = b1[t];
}

// ---- packed f32x2 helpers ----
__device__ __forceinline__ ull dup2(float w) {
    ull r; asm("mov.b64 %0, {%1, %1};" : "=l"(r) : "f"(w)); return r;
}
__device__ __forceinline__ float2 u2f(ull v) {
    float2 f; asm("mov.b64 {%0, %1}, %2;" : "=f"(f.x), "=f"(f.y) : "l"(v)); return f;
}
#define PFMA(acc, w, v) asm("fma.rn.f32x2 %0, %1, %2, %0;" : "+l"(acc) : "l"(w), "l"(v))
__device__ __forceinline__ void addp(ull& a, ull b) {
    asm("add.rn.f32x2 %0, %0, %1;" : "+l"(a) : "l"(b));
}
// acc[0..7] += w * vec16
__device__ __forceinline__ void fma8x2(ull* acc, const float* base, float w) {
    ull ww = dup2(w);
    const ulonglong2* v = (const ulonglong2*)base;
    ulonglong2 a = v[0], b = v[1], c = v[2], d = v[3];
    PFMA(acc[0], ww, a.x); PFMA(acc[1], ww, a.y);
    PFMA(acc[2], ww, b.x); PFMA(acc[3], ww, b.y);
    PFMA(acc[4], ww, c.x); PFMA(acc[5], ww, c.y);
    PFMA(acc[6], ww, d.x); PFMA(acc[7], ww, d.y);
}
// dual: one vec16 feeds two acc sets
__device__ __forceinline__ void fma_dual(ull* a0, ull* a1, const float* base, float w0, float w1) {
    ull W0 = dup2(w0), W1 = dup2(w1);
    const ulonglong2* v = (const ulonglong2*)base;
    ulonglong2 x = v[0], y = v[1], z = v[2], w = v[3];
    PFMA(a0[0], W0, x.x); PFMA(a1[0], W1, x.x);
    PFMA(a0[1], W0, x.y); PFMA(a1[1], W1, x.y);
    PFMA(a0[2], W0, y.x); PFMA(a1[2], W1, y.x);
    PFMA(a0[3], W0, y.y); PFMA(a1[3], W1, y.y);
    PFMA(a0[4], W0, z.x); PFMA(a1[4], W1, z.x);
    PFMA(a0[5], W0, z.y); PFMA(a1[5], W1, z.y);
    PFMA(a0[6], W0, w.x); PFMA(a1[6], W1, w.x);
    PFMA(a0[7], W0, w.y); PFMA(a1[7], W1, w.y);
}

// ---------------- main persistent kernel: 128 CTAs x 16 rows ----------------
__global__ void __launch_bounds__(THREADS, 1)
k_main(const float* __restrict__ u, const float* __restrict__ b2,
       const float* __restrict__ b3, float* __restrict__ out) {
    extern __shared__ float sm[];
    float* A1  = sm;                 // 512*RP
    float* A2  = A1 + 512 * RP;
    float* DH1 = A2 + 512 * RP;
    float* DH2 = DH1 + 512 * RP;
    float* Z   = DH2 + 512 * RP;     // 256*RP
    float* us  = Z + 256 * RP;       // 128*16 u transposed [i][r]
    float* xs  = us + 128 * 16;      // 128*16 x transposed [i][r]

    const int tid  = threadIdx.x;
    const int lane = tid & 31;
    const int row0 = blockIdx.x * R;

    // ---- inline init (replaces k_init): compute x=0 forward pass ----
    for (int t = tid; t < R * 128; t += THREADS) {
        int r = t >> 7, c = t & 127;
        us[c * 16 + r] = u[(row0 + r) * 128 + c];
    }
    float a1v = g_A1init[tid];
    DH1[tid] = fmaxf(a1v, 0.f);          // h1 (temp, stride-1)
    __syncthreads();
    float a2v;
    {
        float acc = b2[origOf(tid)];
#pragma unroll 4
        for (int p = 0; p < 512; ++p) acc = fmaf(g_W2t[p * 512 + tid], DH1[p], acc);
        a2v = acc;
        DH2[tid] = fmaxf(acc, 0.f);      // h2 (temp)
    }
    __syncthreads();
    float zv = 0.f;
    if (tid < 256) {
        float a = b3[tid];
#pragma unroll 4
        for (int q = 0; q < 512; ++q) a = fmaf(g_W3t[q * 256 + tid], DH2[q], a);
        zv = a;
    }
    __syncthreads();
    // replicate x=0 state across R rows
#pragma unroll
    for (int r = 0; r < R; ++r) { A1[tid * RP + r] = a1v; A2[tid * RP + r] = a2v; }
    if (tid < 256) {
#pragma unroll
        for (int r = 0; r < R; ++r) Z[tid * RP + r] = zv;
    }
    float ldacc = 0.f;
    __syncthreads();

    for (int i = 0; i < 128; ++i) {
        // ---- (a) each warp computes x_i redundantly (no barrier) ----
        float xval = 0.f;
        if (lane < 16) {
            float mu = Z[i * RP + lane];
            float sg = Z[(128 + i) * RP + lane];
            xval = us[i * 16 + lane] * __expf(sg) + mu;
            xs[i * 16 + lane] = xval;      // identical duplicate writes
            if (tid < 16) ldacc += sg;
        }
        if (i == 127) break;

        const int s    = 4 * i + (i < 4 ? i : 4);
        const int cols = 512 - s;

        // ---- (c) layer-1 suffix update ----
        {
            int r = tid & 15;
            float x = __shfl_sync(0xffffffffu, xval, r);
            for (int p = s + (tid >> 4); p < 512; p += THREADS / 16) {
                float w   = g_W1c[i * 512 + p];
                float old = A1[p * RP + r];
                float nw  = fmaf(w, x, old);
                A1[p * RP + r]  = nw;
                DH1[p * RP + r] = fmaxf(nw, 0.f) - fmaxf(old, 0.f);
            }
        }
        __syncthreads();

        // ---- (d) A2[q,:] += sum_p W2t[p][q] * DH1[p,:] ----
        if (cols > 256) {
            if (tid < cols) {
                int q = s + tid;
                ull acc[8];
#pragma unroll
                for (int k = 0; k < 8; ++k) acc[k] = 0ull;
#pragma unroll 4
                for (int p = s; p < 512; ++p)
                    fma8x2(acc, DH1 + p * RP, g_W2t[p * 512 + q]);
#pragma unroll
                for (int k = 0; k < 8; ++k) {
                    float2 a = u2f(acc[k]);
                    float o0 = A2[q * RP + 2 * k],     n0 = o0 + a.x;
                    float o1 = A2[q * RP + 2 * k + 1], n1 = o1 + a.y;
                    A2[q * RP + 2 * k]      = n0;
                    A2[q * RP + 2 * k + 1]  = n1;
                    DH2[q * RP + 2 * k]     = fmaxf(n0, 0.f) - fmaxf(o0, 0.f);
                    DH2[q * RP + 2 * k + 1] = fmaxf(n1, 0.f) - fmaxf(o1, 0.f);
                }
            }
        } else {
            // two threads per column, split p-range, one shuffle combine
            int active = 2 * cols;
            if (tid < ((active + 31) & ~31)) {
                int j    = tid >> 1;
                int half = tid & 1;
                int q    = s + (j < cols ? j : cols - 1);
                int mid  = s + (cols >> 1);
                int p0   = half ? mid : s;
                int p1   = half ? 512 : mid;
                ull acc[8];
#pragma unroll
                for (int k = 0; k < 8; ++k) acc[k] = 0ull;
#pragma unroll 4
                for (int p = p0; p < p1; ++p)
                    fma8x2(acc, DH1 + p * RP, g_W2t[p * 512 + q]);
#pragma unroll
                for (int k = 0; k < 8; ++k)
                    addp(acc[k], __shfl_xor_sync(0xffffffffu, acc[k], 1));
                if (half == 0 && j < cols) {
#pragma unroll
                    for (int k = 0; k < 8; ++k) {
                        float2 a = u2f(acc[k]);
                        float o0 = A2[q * RP + 2 * k],     n0 = o0 + a.x;
                        float o1 = A2[q * RP + 2 * k + 1], n1 = o1 + a.y;
                        A2[q * RP + 2 * k]      = n0;
                        A2[q * RP + 2 * k + 1]  = n1;
                        DH2[q * RP + 2 * k]     = fmaxf(n0, 0.f) - fmaxf(o0, 0.f);
                        DH2[q * RP + 2 * k + 1] = fmaxf(n1, 0.f) - fmaxf(o1, 0.f);
                    }
                }
            }
        }
        __syncthreads();

        // ---- (e) z update: thread handles (mu_o, sigma_o), fixed 4-way q-split ----
        {
            int hc = 127 - i;
            int act = (4 * hc + 31) & ~31;
            if (tid < act) {
                int split = tid & 3;
                int jj    = tid >> 2;
                int j     = jj < hc ? jj : hc - 1;
                int o     = i + 1 + j;           // mu col; sigma = o + 128
                int q0    = s + ((split * cols) >> 2);
                int q1    = s + (((split + 1) * cols) >> 2);
                ull am[8], asg[8];
#pragma unroll
                for (int k = 0; k < 8; ++k) { am[k] = 0ull; asg[k] = 0ull; }
#pragma unroll 2
                for (int q = q0; q < q1; ++q) {
                    float wm = g_W3t[q * 256 + o];
                    float ws = g_W3t[q * 256 + o + 128];
                    fma_dual(am, asg, DH2 + q * RP, wm, ws);
                }
#pragma unroll
                for (int off = 1; off <= 2; off <<= 1) {
#pragma unroll
                    for (int k = 0; k < 8; ++k) {
                        addp(am[k],  __shfl_xor_sync(0xffffffffu, am[k],  off));
                        addp(asg[k], __shfl_xor_sync(0xffffffffu, asg[k], off));
                    }
                }
                if (split == 0 && jj < hc) {
#pragma unroll
                    for (int k = 0; k < 8; ++k) {
                        float2 a = u2f(am[k]);
                        Z[o * RP + 2 * k]     += a.x;
                        Z[o * RP + 2 * k + 1] += a.y;
                        float2 b = u2f(asg[k]);
                        Z[(o + 128) * RP + 2 * k]     += b.x;
                        Z[(o + 128) * RP + 2 * k + 1] += b.y;
                    }
                }
            }
        }
        __syncthreads();
    }

    __syncthreads();
    // coalesced writeout
    for (int t = tid; t < R * 128; t += THREADS) {
        int r = t >> 7, c = t & 127;
        out[(row0 + r) * 128 + c] = xs[c * 16 + r];
    }
    if (tid < 16) out[2048 * 128 + row0 + tid] = ldacc;
}

extern "C" void kernel_launch(void* const* d_in, const int* in_sizes, int n_in,
                              void* d_out, int out_size) {
    const float* u  = (const float*)d_in[0];
    const float* W1 = (const float*)d_in[1];
    const float* b1 = (const float*)d_in[2];
    const float* W2 = (const float*)d_in[3];
    const float* b2 = (const float*)d_in[4];
    const float* W3 = (const float*)d_in[5];
    const float* b3 = (const float*)d_in[6];
    const float* m1 = (const float*)d_in[7];
    const float* m2 = (const float*)d_in[8];
    const float* m3 = (const float*)d_in[9];
    float* out = (float*)d_out;

    const size_t smem = (size_t)(512 * RP * 4 + 256 * RP + 128 * 16 * 2) * sizeof(float);
    cudaFuncSetAttribute(k_main, cudaFuncAttributeMaxDynamicSharedMemorySize, (int)smem);

    k_transform<<<256, 256>>>(W1, b1, W2, W3, m1, m2, m3);
    k_main<<<NBLK, THREADS, smem>>>(u, b2, b3, out);
}

// round 6
// speedup vs baseline: 1.1336x; 1.0348x over previous
#include <cuda_runtime.h>
#include <math.h>

// IN_FEATURES=128, UNITS=512, BATCH=2048, out = [x (2048*128) ; logdet (2048)]
#define R        16
#define RP       20      // padded per-unit row stride (floats)
#define THREADS  512
#define NBLK     128

typedef unsigned long long ull;

__device__ float g_W1c[128 * 512];   // [i][p]
__device__ float g_W2t[512 * 512];   // [p][q]
__device__ float g_W3t[512 * 256];   // [q][o]
__device__ float g_A1init[512];      // b1 permuted

__device__ __forceinline__ int posOf(int k) {
    int d = k % 127;
    int j = k / 127;
    return d * 4 + (d < 4 ? d : 4) + j;
}
__device__ __forceinline__ int origOf(int q) {
    int d, j;
    if (q < 20) { d = q / 5; j = q - d * 5; }
    else        { d = 4 + ((q - 20) >> 2); j = (q - 20) & 3; }
    return d + 127 * j;
}

// ---------------- prologue: mask + permute + transpose ----------------
__global__ void k_transform(const float* __restrict__ W1, const float* __restrict__ b1,
                            const float* __restrict__ W2, const float* __restrict__ W3,
                            const float* __restrict__ m1, const float* __restrict__ m2,
                            const float* __restrict__ m3) {
    int idx = blockIdx.x * blockDim.x + threadIdx.x;
    int stride = gridDim.x * blockDim.x;
    for (int t = idx; t < 512 * 128; t += stride) {
        int k = t >> 7, i = t & 127;
        g_W1c[i * 512 + posOf(k)] = W1[t] * m1[t];
    }
    for (int t = idx; t < 512 * 512; t += stride) {
        int m = t >> 9, k = t & 511;
        g_W2t[posOf(k) * 512 + posOf(m)] = W2[t] * m2[t];
    }
    for (int t = idx; t < 256 * 512; t += stride) {
        int o = t >> 9, m = t & 511;
        g_W3t[posOf(m) * 256 + o] = W3[t] * m3[t];
    }
    for (int t = idx; t < 512; t += stride)
        g_A1init[posOf(t)] = b1[t];
}

// ---- packed f32x2 helpers ----
__device__ __forceinline__ ull dup2(float w) {
    ull r; asm("mov.b64 %0, {%1, %1};" : "=l"(r) : "f"(w)); return r;
}
__device__ __forceinline__ float2 u2f(ull v) {
    float2 f; asm("mov.b64 {%0, %1}, %2;" : "=f"(f.x), "=f"(f.y) : "l"(v)); return f;
}
#define PFMA(acc, w, v) asm("fma.rn.f32x2 %0, %1, %2, %0;" : "+l"(acc) : "l"(w), "l"(v))
__device__ __forceinline__ void addp(ull& a, ull b) {
    asm("add.rn.f32x2 %0, %0, %1;" : "+l"(a) : "l"(b));
}
// acc[0..7] += w * vec16 (one smem row, 4 x LDS.128)
__device__ __forceinline__ void fma8x2(ull* acc, const float* base, float w) {
    ull ww = dup2(w);
    const ulonglong2* v = (const ulonglong2*)base;
    ulonglong2 a = v[0], b = v[1], c = v[2], d = v[3];
    PFMA(acc[0], ww, a.x); PFMA(acc[1], ww, a.y);
    PFMA(acc[2], ww, b.x); PFMA(acc[3], ww, b.y);
    PFMA(acc[4], ww, c.x); PFMA(acc[5], ww, c.y);
    PFMA(acc[6], ww, d.x); PFMA(acc[7], ww, d.y);
}
// dual: one vec16 feeds two accumulator sets (2 weight columns)
__device__ __forceinline__ void fma_dual(ull* a0, ull* a1, const float* base, float w0, float w1) {
    ull W0 = dup2(w0), W1 = dup2(w1);
    const ulonglong2* v = (const ulonglong2*)base;
    ulonglong2 x = v[0], y = v[1], z = v[2], w = v[3];
    PFMA(a0[0], W0, x.x); PFMA(a1[0], W1, x.x);
    PFMA(a0[1], W0, x.y); PFMA(a1[1], W1, x.y);
    PFMA(a0[2], W0, y.x); PFMA(a1[2], W1, y.x);
    PFMA(a0[3], W0, y.y); PFMA(a1[3], W1, y.y);
    PFMA(a0[4], W0, z.x); PFMA(a1[4], W1, z.x);
    PFMA(a0[5], W0, z.y); PFMA(a1[5], W1, z.y);
    PFMA(a0[6], W0, w.x); PFMA(a1[6], W1, w.x);
    PFMA(a0[7], W0, w.y); PFMA(a1[7], W1, w.y);
}
// commit a column accumulator into A2/DH2
__device__ __forceinline__ void commit_col(float* A2, float* DH2, int q, const ull* acc) {
#pragma unroll
    for (int k = 0; k < 8; ++k) {
        float2 a = u2f(acc[k]);
        float o0 = A2[q * RP + 2 * k],     n0 = o0 + a.x;
        float o1 = A2[q * RP + 2 * k + 1], n1 = o1 + a.y;
        A2[q * RP + 2 * k]      = n0;
        A2[q * RP + 2 * k + 1]  = n1;
        DH2[q * RP + 2 * k]     = fmaxf(n0, 0.f) - fmaxf(o0, 0.f);
        DH2[q * RP + 2 * k + 1] = fmaxf(n1, 0.f) - fmaxf(o1, 0.f);
    }
}

// ---------------- main persistent kernel: 128 CTAs x 16 rows ----------------
__global__ void __launch_bounds__(THREADS, 1)
k_main(const float* __restrict__ u, const float* __restrict__ b2,
       const float* __restrict__ b3, float* __restrict__ out) {
    extern __shared__ float sm[];
    float* A1  = sm;                 // 512*RP
    float* A2  = A1 + 512 * RP;
    float* DH1 = A2 + 512 * RP;
    float* DH2 = DH1 + 512 * RP;
    float* Z   = DH2 + 512 * RP;     // 256*RP
    float* us  = Z + 256 * RP;       // 128*16 u transposed [i][r]
    float* xs  = us + 128 * 16;      // 128*16 x transposed [i][r]

    const int tid  = threadIdx.x;
    const int lane = tid & 31;
    const int row0 = blockIdx.x * R;

    // ---- inline init: x=0 forward pass (shared state) ----
    for (int t = tid; t < R * 128; t += THREADS) {
        int r = t >> 7, c = t & 127;
        us[c * 16 + r] = u[(row0 + r) * 128 + c];
    }
    float a1v = g_A1init[tid];
    DH1[tid] = fmaxf(a1v, 0.f);
    __syncthreads();
    float a2v;
    {
        float acc = b2[origOf(tid)];
#pragma unroll 4
        for (int p = 0; p < 512; ++p) acc = fmaf(g_W2t[p * 512 + tid], DH1[p], acc);
        a2v = acc;
        DH2[tid] = fmaxf(acc, 0.f);
    }
    __syncthreads();
    float zv = 0.f;
    if (tid < 256) {
        float a = b3[tid];
#pragma unroll 4
        for (int q = 0; q < 512; ++q) a = fmaf(g_W3t[q * 256 + tid], DH2[q], a);
        zv = a;
    }
    __syncthreads();
#pragma unroll
    for (int r = 0; r < R; ++r) { A1[tid * RP + r] = a1v; A2[tid * RP + r] = a2v; }
    if (tid < 256) {
#pragma unroll
        for (int r = 0; r < R; ++r) Z[tid * RP + r] = zv;
    }
    float ldacc = 0.f;
    __syncthreads();

    for (int i = 0; i < 128; ++i) {
        // ---- (a) each warp computes x_i redundantly (no barrier) ----
        float xval = 0.f;
        if (lane < 16) {
            float mu = Z[i * RP + lane];
            float sg = Z[(128 + i) * RP + lane];
            xval = us[i * 16 + lane] * __expf(sg) + mu;
            xs[i * 16 + lane] = xval;      // identical duplicate writes
            if (tid < 16) ldacc += sg;
        }
        if (i == 127) break;

        const int s    = 4 * i + (i < 4 ? i : 4);
        const int cols = 512 - s;

        // ---- (c) layer-1 suffix update ----
        {
            int r = tid & 15;
            float x = __shfl_sync(0xffffffffu, xval, r);
            for (int p = s + (tid >> 4); p < 512; p += THREADS / 16) {
                float w   = g_W1c[i * 512 + p];
                float old = A1[p * RP + r];
                float nw  = fmaf(w, x, old);
                A1[p * RP + r]  = nw;
                DH1[p * RP + r] = fmaxf(nw, 0.f) - fmaxf(old, 0.f);
            }
        }
        __syncthreads();

        // ---- (d) A2[q,:] += sum_p W2t[p][q] * DH1[p,:]  -- q-pair per thread ----
        {
            int npairs = (cols + 1) >> 1;
            if (cols > 256) {
                // pair + 2-way p-split: active = ~cols threads
                int act = (2 * npairs + 31) & ~31;
                if (tid < act) {
                    int j    = tid >> 1;
                    int half = tid & 1;
                    int jc   = j < npairs ? j : npairs - 1;
                    int q0   = s + 2 * jc;
                    bool two = (q0 + 1) < 512;
                    int mid  = s + (cols >> 1);
                    int p0   = half ? mid : s;
                    int p1   = half ? 512 : mid;
                    ull a0[8], a1[8];
#pragma unroll
                    for (int k = 0; k < 8; ++k) { a0[k] = 0ull; a1[k] = 0ull; }
#pragma unroll 2
                    for (int p = p0; p < p1; ++p) {
                        float w0 = g_W2t[p * 512 + q0];
                        float w1 = two ? g_W2t[p * 512 + q0 + 1] : 0.f;
                        fma_dual(a0, a1, DH1 + p * RP, w0, w1);
                    }
#pragma unroll
                    for (int k = 0; k < 8; ++k) {
                        addp(a0[k], __shfl_xor_sync(0xffffffffu, a0[k], 1));
                        addp(a1[k], __shfl_xor_sync(0xffffffffu, a1[k], 1));
                    }
                    if (half == 0 && j < npairs) {
                        commit_col(A2, DH2, q0, a0);
                        if (two) commit_col(A2, DH2, q0 + 1, a1);
                    }
                }
            } else {
                // pair + 4-way p-split: active = ~2*cols threads
                int act = (4 * npairs + 31) & ~31;
                if (tid < act) {
                    int split = tid & 3;
                    int j     = tid >> 2;
                    int jc    = j < npairs ? j : npairs - 1;
                    int q0    = s + 2 * jc;
                    bool two  = (q0 + 1) < 512;
                    int p0    = s + ((split * cols) >> 2);
                    int p1    = s + (((split + 1) * cols) >> 2);
                    ull a0[8], a1[8];
#pragma unroll
                    for (int k = 0; k < 8; ++k) { a0[k] = 0ull; a1[k] = 0ull; }
#pragma unroll 2
                    for (int p = p0; p < p1; ++p) {
                        float w0 = g_W2t[p * 512 + q0];
                        float w1 = two ? g_W2t[p * 512 + q0 + 1] : 0.f;
                        fma_dual(a0, a1, DH1 + p * RP, w0, w1);
                    }
#pragma unroll
                    for (int off = 1; off <= 2; off <<= 1) {
#pragma unroll
                        for (int k = 0; k < 8; ++k) {
                            addp(a0[k], __shfl_xor_sync(0xffffffffu, a0[k], off));
                            addp(a1[k], __shfl_xor_sync(0xffffffffu, a1[k], off));
                        }
                    }
                    if (split == 0 && j < npairs) {
                        commit_col(A2, DH2, q0, a0);
                        if (two) commit_col(A2, DH2, q0 + 1, a1);
                    }
                }
            }
        }
        __syncthreads();

        // ---- (e) z update (R3 scheme): 2 threads per output column ----
        {
            int hc     = 127 - i;
            int ocnt   = 2 * hc;
            int active = 2 * ocnt;
            if (tid < ((active + 31) & ~31)) {
                int j    = tid >> 1;
                int half = tid & 1;
                int jj   = (j < ocnt) ? j : ocnt - 1;
                int o    = (jj < hc) ? (i + 1 + jj) : (129 + i + (jj - hc));
                int mid  = s + (cols >> 1);
                int q0   = half ? mid : s;
                int q1   = half ? 512 : mid;
                ull acc[8];
#pragma unroll
                for (int k = 0; k < 8; ++k) acc[k] = 0ull;
#pragma unroll 4
                for (int q = q0; q < q1; ++q)
                    fma8x2(acc, DH2 + q * RP, g_W3t[q * 256 + o]);
#pragma unroll
                for (int k = 0; k < 8; ++k)
                    addp(acc[k], __shfl_xor_sync(0xffffffffu, acc[k], 1));
                if (half == 0 && j < ocnt) {
#pragma unroll
                    for (int k = 0; k < 8; ++k) {
                        float2 a = u2f(acc[k]);
                        Z[o * RP + 2 * k]     += a.x;
                        Z[o * RP + 2 * k + 1] += a.y;
                    }
                }
            }
        }
        __syncthreads();
    }

    __syncthreads();
    for (int t = tid; t < R * 128; t += THREADS) {
        int r = t >> 7, c = t & 127;
        out[(row0 + r) * 128 + c] = xs[c * 16 + r];
    }
    if (tid < 16) out[2048 * 128 + row0 + tid] = ldacc;
}

extern "C" void kernel_launch(void* const* d_in, const int* in_sizes, int n_in,
                              void* d_out, int out_size) {
    const float* u  = (const float*)d_in[0];
    const float* W1 = (const float*)d_in[1];
    const float* b1 = (const float*)d_in[2];
    const float* W2 = (const float*)d_in[3];
    const float* b2 = (const float*)d_in[4];
    const float* W3 = (const float*)d_in[5];
    const float* b3 = (const float*)d_in[6];
    const float* m1 = (const float*)d_in[7];
    const float* m2 = (const float*)d_in[8];
    const float* m3 = (const float*)d_in[9];
    float* out = (float*)d_out;

    const size_t smem = (size_t)(512 * RP * 4 + 256 * RP + 128 * 16 * 2) * sizeof(float);
    cudaFuncSetAttribute(k_main, cudaFuncAttributeMaxDynamicSharedMemorySize, (int)smem);

    k_transform<<<256, 256>>>(W1, b1, W2, W3, m1, m2, m3);
    k_main<<<NBLK, THREADS, smem>>>(u, b2, b3, out);
}